// round 15
// baseline (speedup 1.0000x reference)
#include <cuda_runtime.h>
#include <stdint.h>

#define L_DIM        1024
#define N_SHIFT      10
#define NBUF         4            // rotating pair-buffers
#define ROWS_PER_CTA 32           // 16 pairs per CTA
#define PAIRS        (ROWS_PER_CTA / 2)
#define PAIR_BYTES   (2 * L_DIM * 4)   // 8 KB per bulk op

// out[b][i][j] = 1.0f iff |i-j| <= 10 and mask[b][p]==0 for all p in
// (min(i,j), max(i,j)].  Per row: contiguous interval [lo, hi] around i.
//
// One-pass bulk-store kernel, v2: 8 KB ops (2 rows) to halve TMA op-service
// overhead; grid sized to exactly one wave at the 32KB-SMEM occupancy limit.

// Compute the row's band interval and write its 1.0f cells into sdst[0..L).
// Verified R12 ballot logic with all three clamps.
__device__ __forceinline__ void write_band_row(const int* __restrict__ mrow,
                                               float* __restrict__ sdst,
                                               int i, int lane) {
    const int j = i + lane - N_SHIFT;            // lane -> j = i-10 .. i+21
    int m = 1;                                    // OOB treated as blocked
    if (j >= 0 && j < L_DIM) m = mrow[j];
    const unsigned bits = __ballot_sync(0xFFFFFFFFu, m != 0);

    const unsigned x = bits << 21;                // lane10 (= mask[i]) -> bit31
    int back = __clz(x);
    if (back > N_SHIFT) back = N_SHIFT;
    if (back > i)       back = i;                 // reach cannot pass j=0

    const unsigned y = bits >> 11;                // lane11 -> bit0
    int fwd = (y == 0u) ? N_SHIFT : (__ffs(y) - 1);
    if (fwd > N_SHIFT) fwd = N_SHIFT;             // lanes 21..31 hold real data

    if (j >= i - back && j <= i + fwd) sdst[j] = 1.0f;  // j in [0,L) guaranteed
}

__global__ __launch_bounds__(32) void band_tma_kernel(const int* __restrict__ mask,
                                                      float* __restrict__ out) {
    __shared__ __align__(128) float buf[NBUF][2 * L_DIM];
    const int lane = threadIdx.x;

    // Zero all buffers once.
    {
        float4* bv = reinterpret_cast<float4*>(&buf[0][0]);
        const float4 z = make_float4(0.f, 0.f, 0.f, 0.f);
        #pragma unroll
        for (int k = lane; k < NBUF * 2 * L_DIM / 4; k += 32) bv[k] = z;
    }
    __syncwarp();

    const int base = blockIdx.x * ROWS_PER_CTA;   // flattened row index b*L + i

    for (int it = 0; it < PAIRS; ++it) {
        const int flat0 = base + it * 2;          // first row of this pair
        float* __restrict__ srow = buf[it & (NBUF - 1)];

        if (it >= NBUF) {
            // Buffer's previous bulk store (NBUF pairs ago) must have drained.
            if (lane == 0)
                asm volatile("cp.async.bulk.wait_group %0;" :: "n"(NBUF - 1) : "memory");
            __syncwarp();
            // Clear previous occupant's band windows (superset of its 1s).
            const int pf0 = flat0 - 2 * NBUF;
            #pragma unroll
            for (int r = 0; r < 2; ++r) {
                const int pi = (pf0 + r) & (L_DIM - 1);
                const int jo = pi + lane - N_SHIFT;
                if (jo >= 0 && jo < L_DIM) srow[r * L_DIM + jo] = 0.0f;
            }
        }

        // Fill both rows' bands.
        #pragma unroll
        for (int r = 0; r < 2; ++r) {
            const int flat = flat0 + r;
            const int i = flat & (L_DIM - 1);
            const int b = flat >> 10;
            write_band_row(mask + ((size_t)b << 10), srow + r * L_DIM, i, lane);
        }
        __syncwarp();

        // Emit the 8 KB pair via bulk async store.
        if (lane == 0) {
            asm volatile("fence.proxy.async.shared::cta;" ::: "memory");
            uint32_t saddr;
            asm("{ .reg .u64 t; cvta.to.shared.u64 t, %1; cvt.u32.u64 %0, t; }"
                : "=r"(saddr) : "l"(srow));
            asm volatile("cp.async.bulk.global.shared::cta.bulk_group [%0], [%1], %2;"
                         :: "l"(out + ((size_t)flat0 << 10)), "r"(saddr), "r"(PAIR_BYTES)
                         : "memory");
            asm volatile("cp.async.bulk.commit_group;" ::: "memory");
        }
    }

    // Drain all outstanding stores before the buffers go out of scope.
    if (lane == 0)
        asm volatile("cp.async.bulk.wait_group 0;" ::: "memory");
}

extern "C" void kernel_launch(void* const* d_in, const int* in_sizes, int n_in,
                              void* d_out, int out_size) {
    const int* mask = (const int*)d_in[0];
    float* out = (float*)d_out;

    const int rows = in_sizes[0];                 // B * L = 32768
    const int ncta = rows / ROWS_PER_CTA;         // 1024

    band_tma_kernel<<<ncta, 32>>>(mask, out);
}